// round 12
// baseline (speedup 1.0000x reference)
#include <cuda_runtime.h>
#include <math.h>

// ---------------------------------------------------------------------------
// Problem constants
// ---------------------------------------------------------------------------
#define NB 4
#define SS 4096
#define DD 1024
#define HH 16
#define HD 64
#define FF 4096
#define TT (NB*SS)      // 16384 tokens

// ---------------------------------------------------------------------------
// Scratch (device globals; no allocations allowed)
// ---------------------------------------------------------------------------
__device__ float g_x[(size_t)TT*DD];     // x after LN1 (FFN input / residual)
__device__ float g_q[(size_t)TT*DD];
__device__ float g_k[(size_t)TT*DD];
__device__ float g_v[(size_t)TT*DD];
__device__ float g_a[(size_t)TT*DD];     // attention output
__device__ float g_t[(size_t)TT*DD];     // pre-LN sum buffer
__device__ float g_h[(size_t)TT*FF];     // FFN hidden
__device__ float g_kvt[NB*HH*HD*HD];     // KV^T per head: [nh][d][m]
__device__ float g_ksum[NB*HH*HD];
__device__ int   g_vlen[NB];

enum { EPI_NONE = 0, EPI_Q = 1, EPI_K = 2, EPI_GELU = 3, EPI_RES = 4 };

// ---------------------------------------------------------------------------
// valid length per batch (LengthMask semantics: S - count(padding))
// ---------------------------------------------------------------------------
__global__ void vlen_kernel(const unsigned char* __restrict__ mask) {
    int n = blockIdx.x;
    __shared__ int sh[256];
    int cnt = 0;
    for (int s = threadIdx.x; s < SS; s += 256) cnt += (mask[(size_t)n*SS + s] != 0);
    sh[threadIdx.x] = cnt;
    __syncthreads();
    for (int o = 128; o > 0; o >>= 1) {
        if (threadIdx.x < o) sh[threadIdx.x] += sh[threadIdx.x + o];
        __syncthreads();
    }
    if (threadIdx.x == 0) g_vlen[n] = SS - sh[0];
}

// ---------------------------------------------------------------------------
// fp32 NT GEMM: C[M,N] = A[M,K] @ B[N,K]^T + bias, fused epilogue.
// 128x128 block tile, BK=16, 256 threads, 8x8 per-thread microtile.
// M, N multiples of 128; K multiple of 16. Rows map to tokens (n = row>>12).
// ---------------------------------------------------------------------------
__global__ __launch_bounds__(256, 2)
void gemm_nt(const float* __restrict__ A, const float* __restrict__ B,
             const float* __restrict__ bias, const float* __restrict__ resid,
             float* __restrict__ C, int M, int N, int K, int epi)
{
    __shared__ float As[16][128];
    __shared__ float Bs[16][128];

    const int tid = threadIdx.x;
    const int rowBase = blockIdx.y * 128;
    const int colBase = blockIdx.x * 128;
    const float* Ab = A + (size_t)rowBase * K;
    const float* Bb = B + (size_t)colBase * K;

    float acc[8][8];
#pragma unroll
    for (int i = 0; i < 8; i++)
#pragma unroll
        for (int j = 0; j < 8; j++) acc[i][j] = 0.f;

    const int tr = (tid >> 4) * 8;
    const int tc = (tid & 15) * 8;

    for (int k0 = 0; k0 < K; k0 += 16) {
#pragma unroll
        for (int l = 0; l < 2; l++) {
            int li = tid + l * 256;            // 512 float4 per tile
            int r  = li >> 2;
            int c  = (li & 3) * 4;
            float4 fa = *(const float4*)(Ab + (size_t)r * K + k0 + c);
            As[c + 0][r] = fa.x; As[c + 1][r] = fa.y;
            As[c + 2][r] = fa.z; As[c + 3][r] = fa.w;
            float4 fb = *(const float4*)(Bb + (size_t)r * K + k0 + c);
            Bs[c + 0][r] = fb.x; Bs[c + 1][r] = fb.y;
            Bs[c + 2][r] = fb.z; Bs[c + 3][r] = fb.w;
        }
        __syncthreads();

#pragma unroll
        for (int kk = 0; kk < 16; kk++) {
            float ar[8], br[8];
            *(float4*)(ar)     = *(const float4*)&As[kk][tr];
            *(float4*)(ar + 4) = *(const float4*)&As[kk][tr + 4];
            *(float4*)(br)     = *(const float4*)&Bs[kk][tc];
            *(float4*)(br + 4) = *(const float4*)&Bs[kk][tc + 4];
#pragma unroll
            for (int i = 0; i < 8; i++)
#pragma unroll
                for (int j = 0; j < 8; j++) acc[i][j] += ar[i] * br[j];
        }
        __syncthreads();
    }

    // epilogue
#pragma unroll
    for (int i = 0; i < 8; i++) {
        int row  = rowBase + tr + i;
        int sIdx = row & (SS - 1);
        int nIdx = row >> 12;
        float fm = 1.f;
        if (epi == EPI_K) fm = (sIdx < g_vlen[nIdx]) ? 1.f : 0.f;
#pragma unroll
        for (int jj = 0; jj < 8; jj += 4) {
            float4 o;
            float* op = &o.x;
#pragma unroll
            for (int j = 0; j < 4; j++) {
                int col = colBase + tc + jj + j;
                float v = acc[i][jj + j] + bias[col];
                if (epi == EPI_Q || epi == EPI_K) {
                    v = (v > 0.f ? v + 1.f : __expf(v)) * fm;   // elu(v)+1
                } else if (epi == EPI_GELU) {
                    v = 0.5f * v * (1.f + erff(v * 0.70710678118654752f));
                } else if (epi == EPI_RES) {
                    v += resid[(size_t)row * N + col];
                }
                op[j] = v;
            }
            *(float4*)(C + (size_t)row * N + colBase + tc + jj) = o;
        }
    }
}

// ---------------------------------------------------------------------------
// KV^T + Ksum per (n,h): KV[m][d] = sum_s K[s][d]*V[s][m]; store as [d][m].
// 64 blocks (one per head-batch), 256 threads, 4x4 per thread.
// ---------------------------------------------------------------------------
__global__ __launch_bounds__(256, 1)
void kv_kernel(const float* __restrict__ Kf, const float* __restrict__ Vf)
{
    __shared__ float Ks[32][64];
    __shared__ float Vs[32][64];

    const int nh = blockIdx.x;
    const int n = nh >> 4, h = nh & 15;
    const int tid = threadIdx.x;
    const int tm = tid >> 4, tn = tid & 15;
    const int m0 = tm * 4, d0 = tn * 4;

    float acc[4][4] = {};
    float ks[4] = {};

    const float* Kb = Kf + ((size_t)n * SS) * DD + h * HD;
    const float* Vb = Vf + ((size_t)n * SS) * DD + h * HD;

    for (int s0 = 0; s0 < SS; s0 += 32) {
#pragma unroll
        for (int l = 0; l < 2; l++) {
            int li = tid + l * 256;            // 512 float4 = 32 rows x 16
            int r  = li >> 4;
            int c  = (li & 15) * 4;
            *(float4*)&Ks[r][c] = *(const float4*)(Kb + (size_t)(s0 + r) * DD + c);
            *(float4*)&Vs[r][c] = *(const float4*)(Vb + (size_t)(s0 + r) * DD + c);
        }
        __syncthreads();
#pragma unroll 8
        for (int ss = 0; ss < 32; ss++) {
            float kd[4], vm[4];
            *(float4*)kd = *(const float4*)&Ks[ss][d0];
            *(float4*)vm = *(const float4*)&Vs[ss][m0];
#pragma unroll
            for (int mi = 0; mi < 4; mi++)
#pragma unroll
                for (int di = 0; di < 4; di++) acc[mi][di] += vm[mi] * kd[di];
            if (tm == 0) {
                ks[0] += kd[0]; ks[1] += kd[1]; ks[2] += kd[2]; ks[3] += kd[3];
            }
        }
        __syncthreads();
    }

    float* kvb = g_kvt + (size_t)nh * HD * HD;
#pragma unroll
    for (int mi = 0; mi < 4; mi++)
#pragma unroll
        for (int di = 0; di < 4; di++)
            kvb[(d0 + di) * HD + (m0 + mi)] = acc[mi][di];
    if (tm == 0)
#pragma unroll
        for (int di = 0; di < 4; di++) g_ksum[nh * HD + d0 + di] = ks[di];
}

// ---------------------------------------------------------------------------
// attn[l][m] = z * sum_d Q[l][d] * KV^T[d][m],  z = 1/(Q.Ksum + eps)
// grid (64 head-batches, 64 token-chunks of 64), 256 threads = 8 warps,
// one warp per token, KV^T staged in smem (conflict-free: lane indexes m).
// ---------------------------------------------------------------------------
__global__ __launch_bounds__(256, 1)
void attn_kernel(const float* __restrict__ Qf, float* __restrict__ Af)
{
    __shared__ float KVs[64 * 64];
    __shared__ float ksm[64];
    __shared__ float Qs[8][64];

    const int nh = blockIdx.x;
    const int n = nh >> 4, h = nh & 15;
    const int tBase = blockIdx.y * 64;
    const int tid = threadIdx.x, lane = tid & 31, w = tid >> 5;

    const float* kvb = g_kvt + (size_t)nh * 4096;
    for (int i = tid; i < 1024; i += 256)
        *(float4*)&KVs[i * 4] = *(const float4*)&kvb[i * 4];
    if (tid < 64) ksm[tid] = g_ksum[nh * 64 + tid];
    __syncthreads();

    const float* Qb = Qf + ((size_t)n * SS) * DD + h * HD;
    float* Ab = Af + ((size_t)n * SS) * DD + h * HD;

    for (int g = 0; g < 8; g++) {
        int t0 = tBase + g * 8;
        if (tid < 128) {
            int r = tid >> 4, c = (tid & 15) * 4;
            *(float4*)&Qs[r][c] = *(const float4*)(Qb + (size_t)(t0 + r) * DD + c);
        }
        __syncthreads();

        float p = Qs[w][lane] * ksm[lane] + Qs[w][lane + 32] * ksm[lane + 32];
#pragma unroll
        for (int o = 16; o; o >>= 1) p += __shfl_xor_sync(0xffffffffu, p, o);
        float z = 1.f / (p + 1e-6f);

        float a0 = 0.f, a1 = 0.f;
#pragma unroll
        for (int d = 0; d < 64; d++) {
            float qd = Qs[w][d];
            a0 += qd * KVs[d * 64 + lane];
            a1 += qd * KVs[d * 64 + lane + 32];
        }
        float* op = Ab + (size_t)(t0 + w) * DD;
        op[lane]      = a0 * z;
        op[lane + 32] = a1 * z;
        __syncthreads();
    }
}

// ---------------------------------------------------------------------------
// LayerNorm over D=1024 (one block per row, 256 threads, float4 per thread)
// ---------------------------------------------------------------------------
__global__ __launch_bounds__(256, 4)
void ln_kernel(const float* __restrict__ X, const float* __restrict__ G,
               const float* __restrict__ B, float* __restrict__ Y)
{
    __shared__ float s1[8], s2[8];
    const int row = blockIdx.x, tid = threadIdx.x;
    const int lane = tid & 31, w = tid >> 5;

    float4 x = ((const float4*)(X + (size_t)row * DD))[tid];
    float s = x.x + x.y + x.z + x.w;
    float q = x.x*x.x + x.y*x.y + x.z*x.z + x.w*x.w;
#pragma unroll
    for (int o = 16; o; o >>= 1) {
        s += __shfl_xor_sync(0xffffffffu, s, o);
        q += __shfl_xor_sync(0xffffffffu, q, o);
    }
    if (lane == 0) { s1[w] = s; s2[w] = q; }
    __syncthreads();
    float st = 0.f, qt = 0.f;
#pragma unroll
    for (int i = 0; i < 8; i++) { st += s1[i]; qt += s2[i]; }

    float mu  = st * (1.f / DD);
    float var = qt * (1.f / DD) - mu * mu;
    float rs  = rsqrtf(var + 1e-5f);

    float4 g = ((const float4*)G)[tid];
    float4 b = ((const float4*)B)[tid];
    float4 o;
    o.x = (x.x - mu) * rs * g.x + b.x;
    o.y = (x.y - mu) * rs * g.y + b.y;
    o.z = (x.z - mu) * rs * g.z + b.z;
    o.w = (x.w - mu) * rs * g.w + b.w;
    ((float4*)(Y + (size_t)row * DD))[tid] = o;
}

// ---------------------------------------------------------------------------
// launch
// ---------------------------------------------------------------------------
extern "C" void kernel_launch(void* const* d_in, const int* in_sizes, int n_in,
                              void* d_out, int out_size)
{
    (void)in_sizes; (void)n_in; (void)out_size;

    const float* src = (const float*)d_in[0];
    const unsigned char* mask = (const unsigned char*)d_in[1];
    const float* Wq = (const float*)d_in[2];
    const float* bq = (const float*)d_in[3];
    const float* Wk = (const float*)d_in[4];
    const float* bk = (const float*)d_in[5];
    const float* Wv = (const float*)d_in[6];
    const float* bv = (const float*)d_in[7];
    const float* Wo = (const float*)d_in[8];
    const float* bo = (const float*)d_in[9];
    const float* W1 = (const float*)d_in[10];
    const float* b1 = (const float*)d_in[11];
    const float* W2 = (const float*)d_in[12];
    const float* b2 = (const float*)d_in[13];
    const float* g1 = (const float*)d_in[14];
    const float* be1 = (const float*)d_in[15];
    const float* g2 = (const float*)d_in[16];
    const float* be2 = (const float*)d_in[17];

    float *x, *q, *k, *v, *a, *t, *h;
    cudaGetSymbolAddress((void**)&x, g_x);
    cudaGetSymbolAddress((void**)&q, g_q);
    cudaGetSymbolAddress((void**)&k, g_k);
    cudaGetSymbolAddress((void**)&v, g_v);
    cudaGetSymbolAddress((void**)&a, g_a);
    cudaGetSymbolAddress((void**)&t, g_t);
    cudaGetSymbolAddress((void**)&h, g_h);

    vlen_kernel<<<NB, 256>>>(mask);

    const dim3 gD(DD / 128, TT / 128);   // 8 x 128 blocks
    const dim3 gF(FF / 128, TT / 128);   // 32 x 128 blocks

    const float* xc = src;
    for (int i = 0; i < 4; i++) {
        const size_t wD = (size_t)i * DD * DD;
        const size_t wF = (size_t)i * FF * DD;

        gemm_nt<<<gD, 256>>>(xc, Wq + wD, bq + i * DD, nullptr, q, TT, DD, DD, EPI_Q);
        gemm_nt<<<gD, 256>>>(xc, Wk + wD, bk + i * DD, nullptr, k, TT, DD, DD, EPI_K);
        gemm_nt<<<gD, 256>>>(xc, Wv + wD, bv + i * DD, nullptr, v, TT, DD, DD, EPI_NONE);

        kv_kernel<<<NB * HH, 256>>>(k, v);
        attn_kernel<<<dim3(NB * HH, SS / 64), 256>>>(q, a);

        gemm_nt<<<gD, 256>>>(a, Wo + wD, bo + i * DD, xc, t, TT, DD, DD, EPI_RES);
        ln_kernel<<<TT, 256>>>(t, g1 + i * DD, be1 + i * DD, x);

        gemm_nt<<<gF, 256>>>(x, W1 + wF, b1 + i * FF, nullptr, h, TT, FF, DD, EPI_GELU);
        gemm_nt<<<gD, 256>>>(h, W2 + wF, b2 + i * DD, x, t, TT, DD, FF, EPI_RES);
        ln_kernel<<<TT, 256>>>(t, g2 + i * DD, be2 + i * DD,
                               (i == 3) ? (float*)d_out : x);
        xc = x;
    }
}

// round 13
// speedup vs baseline: 1.0010x; 1.0010x over previous
#include <cuda_runtime.h>
#include <math.h>

// ---------------------------------------------------------------------------
// Problem constants
// ---------------------------------------------------------------------------
#define NB 4
#define SS 4096
#define DD 1024
#define HH 16
#define HD 64
#define FF 4096
#define TT (NB*SS)      // 16384 tokens

// ---------------------------------------------------------------------------
// Scratch (device globals; no allocations allowed)
// ---------------------------------------------------------------------------
__device__ float g_x[(size_t)TT*DD];     // x after LN1 (FFN input / residual)
__device__ float g_q[(size_t)TT*DD];
__device__ float g_k[(size_t)TT*DD];
__device__ float g_v[(size_t)TT*DD];
__device__ float g_a[(size_t)TT*DD];     // attention output
__device__ float g_t[(size_t)TT*DD];     // pre-LN sum buffer
__device__ float g_h[(size_t)TT*FF];     // FFN hidden
__device__ float g_kvt[NB*HH*HD*HD];     // KV^T per head: [nh][d][m]
__device__ float g_ksum[NB*HH*HD];
__device__ int   g_vlen[NB];

enum { EPI_NONE = 0, EPI_Q = 1, EPI_K = 2, EPI_GELU = 3, EPI_RES = 4 };

// ---------------------------------------------------------------------------
// valid length per batch (LengthMask semantics: S - count(padding))
// ---------------------------------------------------------------------------
__global__ void vlen_kernel(const unsigned char* __restrict__ mask) {
    int n = blockIdx.x;
    __shared__ int sh[256];
    int cnt = 0;
    for (int s = threadIdx.x; s < SS; s += 256) cnt += (mask[(size_t)n*SS + s] != 0);
    sh[threadIdx.x] = cnt;
    __syncthreads();
    for (int o = 128; o > 0; o >>= 1) {
        if (threadIdx.x < o) sh[threadIdx.x] += sh[threadIdx.x + o];
        __syncthreads();
    }
    if (threadIdx.x == 0) g_vlen[n] = SS - sh[0];
}

// ---------------------------------------------------------------------------
// fp32 NT GEMM: C[M,N] = A[M,K] @ B[N,K]^T + bias, fused epilogue.
// 128x128 block tile, BK=16, 256 threads, 8x8 per-thread microtile.
// M, N multiples of 128; K multiple of 16. Rows map to tokens (n = row>>12).
// ---------------------------------------------------------------------------
__global__ __launch_bounds__(256, 2)
void gemm_nt(const float* __restrict__ A, const float* __restrict__ B,
             const float* __restrict__ bias, const float* __restrict__ resid,
             float* __restrict__ C, int M, int N, int K, int epi)
{
    __shared__ float As[16][128];
    __shared__ float Bs[16][128];

    const int tid = threadIdx.x;
    const int rowBase = blockIdx.y * 128;
    const int colBase = blockIdx.x * 128;
    const float* Ab = A + (size_t)rowBase * K;
    const float* Bb = B + (size_t)colBase * K;

    float acc[8][8];
#pragma unroll
    for (int i = 0; i < 8; i++)
#pragma unroll
        for (int j = 0; j < 8; j++) acc[i][j] = 0.f;

    const int tr = (tid >> 4) * 8;
    const int tc = (tid & 15) * 8;

    for (int k0 = 0; k0 < K; k0 += 16) {
#pragma unroll
        for (int l = 0; l < 2; l++) {
            int li = tid + l * 256;            // 512 float4 per tile
            int r  = li >> 2;
            int c  = (li & 3) * 4;
            float4 fa = *(const float4*)(Ab + (size_t)r * K + k0 + c);
            As[c + 0][r] = fa.x; As[c + 1][r] = fa.y;
            As[c + 2][r] = fa.z; As[c + 3][r] = fa.w;
            float4 fb = *(const float4*)(Bb + (size_t)r * K + k0 + c);
            Bs[c + 0][r] = fb.x; Bs[c + 1][r] = fb.y;
            Bs[c + 2][r] = fb.z; Bs[c + 3][r] = fb.w;
        }
        __syncthreads();

#pragma unroll
        for (int kk = 0; kk < 16; kk++) {
            float ar[8], br[8];
            *(float4*)(ar)     = *(const float4*)&As[kk][tr];
            *(float4*)(ar + 4) = *(const float4*)&As[kk][tr + 4];
            *(float4*)(br)     = *(const float4*)&Bs[kk][tc];
            *(float4*)(br + 4) = *(const float4*)&Bs[kk][tc + 4];
#pragma unroll
            for (int i = 0; i < 8; i++)
#pragma unroll
                for (int j = 0; j < 8; j++) acc[i][j] += ar[i] * br[j];
        }
        __syncthreads();
    }

    // epilogue
#pragma unroll
    for (int i = 0; i < 8; i++) {
        int row  = rowBase + tr + i;
        int sIdx = row & (SS - 1);
        int nIdx = row >> 12;
        float fm = 1.f;
        if (epi == EPI_K) fm = (sIdx < g_vlen[nIdx]) ? 1.f : 0.f;
#pragma unroll
        for (int jj = 0; jj < 8; jj += 4) {
            float4 o;
            float* op = &o.x;
#pragma unroll
            for (int j = 0; j < 4; j++) {
                int col = colBase + tc + jj + j;
                float v = acc[i][jj + j] + bias[col];
                if (epi == EPI_Q || epi == EPI_K) {
                    v = (v > 0.f ? v + 1.f : __expf(v)) * fm;   // elu(v)+1
                } else if (epi == EPI_GELU) {
                    v = 0.5f * v * (1.f + erff(v * 0.70710678118654752f));
                } else if (epi == EPI_RES) {
                    v += resid[(size_t)row * N + col];
                }
                op[j] = v;
            }
            *(float4*)(C + (size_t)row * N + colBase + tc + jj) = o;
        }
    }
}

// ---------------------------------------------------------------------------
// KV^T + Ksum per (n,h): KV[m][d] = sum_s K[s][d]*V[s][m]; store as [d][m].
// 64 blocks (one per head-batch), 256 threads, 4x4 per thread.
// ---------------------------------------------------------------------------
__global__ __launch_bounds__(256, 1)
void kv_kernel(const float* __restrict__ Kf, const float* __restrict__ Vf)
{
    __shared__ float Ks[32][64];
    __shared__ float Vs[32][64];

    const int nh = blockIdx.x;
    const int n = nh >> 4, h = nh & 15;
    const int tid = threadIdx.x;
    const int tm = tid >> 4, tn = tid & 15;
    const int m0 = tm * 4, d0 = tn * 4;

    float acc[4][4] = {};
    float ks[4] = {};

    const float* Kb = Kf + ((size_t)n * SS) * DD + h * HD;
    const float* Vb = Vf + ((size_t)n * SS) * DD + h * HD;

    for (int s0 = 0; s0 < SS; s0 += 32) {
#pragma unroll
        for (int l = 0; l < 2; l++) {
            int li = tid + l * 256;            // 512 float4 = 32 rows x 16
            int r  = li >> 4;
            int c  = (li & 15) * 4;
            *(float4*)&Ks[r][c] = *(const float4*)(Kb + (size_t)(s0 + r) * DD + c);
            *(float4*)&Vs[r][c] = *(const float4*)(Vb + (size_t)(s0 + r) * DD + c);
        }
        __syncthreads();
#pragma unroll 8
        for (int ss = 0; ss < 32; ss++) {
            float kd[4], vm[4];
            *(float4*)kd = *(const float4*)&Ks[ss][d0];
            *(float4*)vm = *(const float4*)&Vs[ss][m0];
#pragma unroll
            for (int mi = 0; mi < 4; mi++)
#pragma unroll
                for (int di = 0; di < 4; di++) acc[mi][di] += vm[mi] * kd[di];
            if (tm == 0) {
                ks[0] += kd[0]; ks[1] += kd[1]; ks[2] += kd[2]; ks[3] += kd[3];
            }
        }
        __syncthreads();
    }

    float* kvb = g_kvt + (size_t)nh * HD * HD;
#pragma unroll
    for (int mi = 0; mi < 4; mi++)
#pragma unroll
        for (int di = 0; di < 4; di++)
            kvb[(d0 + di) * HD + (m0 + mi)] = acc[mi][di];
    if (tm == 0)
#pragma unroll
        for (int di = 0; di < 4; di++) g_ksum[nh * HD + d0 + di] = ks[di];
}

// ---------------------------------------------------------------------------
// attn[l][m] = z * sum_d Q[l][d] * KV^T[d][m],  z = 1/(Q.Ksum + eps)
// grid (64 head-batches, 64 token-chunks of 64), 256 threads = 8 warps,
// one warp per token, KV^T staged in smem (conflict-free: lane indexes m).
// ---------------------------------------------------------------------------
__global__ __launch_bounds__(256, 1)
void attn_kernel(const float* __restrict__ Qf, float* __restrict__ Af)
{
    __shared__ float KVs[64 * 64];
    __shared__ float ksm[64];
    __shared__ float Qs[8][64];

    const int nh = blockIdx.x;
    const int n = nh >> 4, h = nh & 15;
    const int tBase = blockIdx.y * 64;
    const int tid = threadIdx.x, lane = tid & 31, w = tid >> 5;

    const float* kvb = g_kvt + (size_t)nh * 4096;
    for (int i = tid; i < 1024; i += 256)
        *(float4*)&KVs[i * 4] = *(const float4*)&kvb[i * 4];
    if (tid < 64) ksm[tid] = g_ksum[nh * 64 + tid];
    __syncthreads();

    const float* Qb = Qf + ((size_t)n * SS) * DD + h * HD;
    float* Ab = Af + ((size_t)n * SS) * DD + h * HD;

    for (int g = 0; g < 8; g++) {
        int t0 = tBase + g * 8;
        if (tid < 128) {
            int r = tid >> 4, c = (tid & 15) * 4;
            *(float4*)&Qs[r][c] = *(const float4*)(Qb + (size_t)(t0 + r) * DD + c);
        }
        __syncthreads();

        float p = Qs[w][lane] * ksm[lane] + Qs[w][lane + 32] * ksm[lane + 32];
#pragma unroll
        for (int o = 16; o; o >>= 1) p += __shfl_xor_sync(0xffffffffu, p, o);
        float z = 1.f / (p + 1e-6f);

        float a0 = 0.f, a1 = 0.f;
#pragma unroll
        for (int d = 0; d < 64; d++) {
            float qd = Qs[w][d];
            a0 += qd * KVs[d * 64 + lane];
            a1 += qd * KVs[d * 64 + lane + 32];
        }
        float* op = Ab + (size_t)(t0 + w) * DD;
        op[lane]      = a0 * z;
        op[lane + 32] = a1 * z;
        __syncthreads();
    }
}

// ---------------------------------------------------------------------------
// LayerNorm over D=1024 (one block per row, 256 threads, float4 per thread)
// ---------------------------------------------------------------------------
__global__ __launch_bounds__(256, 4)
void ln_kernel(const float* __restrict__ X, const float* __restrict__ G,
               const float* __restrict__ B, float* __restrict__ Y)
{
    __shared__ float s1[8], s2[8];
    const int row = blockIdx.x, tid = threadIdx.x;
    const int lane = tid & 31, w = tid >> 5;

    float4 x = ((const float4*)(X + (size_t)row * DD))[tid];
    float s = x.x + x.y + x.z + x.w;
    float q = x.x*x.x + x.y*x.y + x.z*x.z + x.w*x.w;
#pragma unroll
    for (int o = 16; o; o >>= 1) {
        s += __shfl_xor_sync(0xffffffffu, s, o);
        q += __shfl_xor_sync(0xffffffffu, q, o);
    }
    if (lane == 0) { s1[w] = s; s2[w] = q; }
    __syncthreads();
    float st = 0.f, qt = 0.f;
#pragma unroll
    for (int i = 0; i < 8; i++) { st += s1[i]; qt += s2[i]; }

    float mu  = st * (1.f / DD);
    float var = qt * (1.f / DD) - mu * mu;
    float rs  = rsqrtf(var + 1e-5f);

    float4 g = ((const float4*)G)[tid];
    float4 b = ((const float4*)B)[tid];
    float4 o;
    o.x = (x.x - mu) * rs * g.x + b.x;
    o.y = (x.y - mu) * rs * g.y + b.y;
    o.z = (x.z - mu) * rs * g.z + b.z;
    o.w = (x.w - mu) * rs * g.w + b.w;
    ((float4*)(Y + (size_t)row * DD))[tid] = o;
}

// ---------------------------------------------------------------------------
// launch
// ---------------------------------------------------------------------------
extern "C" void kernel_launch(void* const* d_in, const int* in_sizes, int n_in,
                              void* d_out, int out_size)
{
    (void)in_sizes; (void)n_in; (void)out_size;

    const float* src = (const float*)d_in[0];
    const unsigned char* mask = (const unsigned char*)d_in[1];
    const float* Wq = (const float*)d_in[2];
    const float* bq = (const float*)d_in[3];
    const float* Wk = (const float*)d_in[4];
    const float* bk = (const float*)d_in[5];
    const float* Wv = (const float*)d_in[6];
    const float* bv = (const float*)d_in[7];
    const float* Wo = (const float*)d_in[8];
    const float* bo = (const float*)d_in[9];
    const float* W1 = (const float*)d_in[10];
    const float* b1 = (const float*)d_in[11];
    const float* W2 = (const float*)d_in[12];
    const float* b2 = (const float*)d_in[13];
    const float* g1 = (const float*)d_in[14];
    const float* be1 = (const float*)d_in[15];
    const float* g2 = (const float*)d_in[16];
    const float* be2 = (const float*)d_in[17];

    float *x, *q, *k, *v, *a, *t, *h;
    cudaGetSymbolAddress((void**)&x, g_x);
    cudaGetSymbolAddress((void**)&q, g_q);
    cudaGetSymbolAddress((void**)&k, g_k);
    cudaGetSymbolAddress((void**)&v, g_v);
    cudaGetSymbolAddress((void**)&a, g_a);
    cudaGetSymbolAddress((void**)&t, g_t);
    cudaGetSymbolAddress((void**)&h, g_h);

    vlen_kernel<<<NB, 256>>>(mask);

    const dim3 gD(DD / 128, TT / 128);   // 8 x 128 blocks
    const dim3 gF(FF / 128, TT / 128);   // 32 x 128 blocks

    const float* xc = src;
    for (int i = 0; i < 4; i++) {
        const size_t wD = (size_t)i * DD * DD;
        const size_t wF = (size_t)i * FF * DD;

        gemm_nt<<<gD, 256>>>(xc, Wq + wD, bq + i * DD, nullptr, q, TT, DD, DD, EPI_Q);
        gemm_nt<<<gD, 256>>>(xc, Wk + wD, bk + i * DD, nullptr, k, TT, DD, DD, EPI_K);
        gemm_nt<<<gD, 256>>>(xc, Wv + wD, bv + i * DD, nullptr, v, TT, DD, DD, EPI_NONE);

        kv_kernel<<<NB * HH, 256>>>(k, v);
        attn_kernel<<<dim3(NB * HH, SS / 64), 256>>>(q, a);

        gemm_nt<<<gD, 256>>>(a, Wo + wD, bo + i * DD, xc, t, TT, DD, DD, EPI_RES);
        ln_kernel<<<TT, 256>>>(t, g1 + i * DD, be1 + i * DD, x);

        gemm_nt<<<gF, 256>>>(x, W1 + wF, b1 + i * FF, nullptr, h, TT, FF, DD, EPI_GELU);
        gemm_nt<<<gD, 256>>>(h, W2 + wF, b2 + i * DD, x, t, TT, DD, FF, EPI_RES);
        ln_kernel<<<TT, 256>>>(t, g2 + i * DD, be2 + i * DD,
                               (i == 3) ? (float*)d_out : x);
        xc = x;
    }
}